// round 3
// baseline (speedup 1.0000x reference)
#include <cuda_runtime.h>
#include <cuda_bf16.h>
#include <math.h>

// Problem constants
#define BB 16
#define NN 1024
#define DD 128
#define HH 8
#define DH 16
#define NTOK (BB*NN)        // 16384
#define KPAD 132            // padded K for GEMM smem tiles

typedef unsigned long long ull;

// ---------------- packed f32x2 helpers (sm_103a FFMA2 path) ----------------
__device__ __forceinline__ ull pack2(float x, float y) {
    ull r; asm("mov.b64 %0, {%1, %2};" : "=l"(r) : "f"(x), "f"(y)); return r;
}
__device__ __forceinline__ void unpack2(ull v, float& x, float& y) {
    asm("mov.b64 {%0, %1}, %2;" : "=f"(x), "=f"(y) : "l"(v));
}
__device__ __forceinline__ ull fma2(ull a, ull b, ull c) {
    ull d; asm("fma.rn.f32x2 %0, %1, %2, %3;" : "=l"(d) : "l"(a), "l"(b), "l"(c)); return d;
}
__device__ __forceinline__ ull mul2(ull a, ull b) {
    ull d; asm("mul.rn.f32x2 %0, %1, %2;" : "=l"(d) : "l"(a), "l"(b)); return d;
}

// ---------------- scratch (static device memory; no allocation) ----------------
__device__ float g_eeig[NTOK * KPAD];     // sine-encoded features, zero-padded to 132
__device__ float g_eig [NTOK * DD];       // residual stream
__device__ float g_h   [NTOK * DD];       // LN output
__device__ float g_qkv [NTOK * 3*DD];     // q,k,v
__device__ float g_att [NTOK * DD];       // attention out; reused as FFN hidden
__device__ float g_pool[BB * 20];         // pooled decoder sums
__device__ float g_coe [BB * 20];         // coe_sca[8], coe_wav[8], coe_scl[4]

// ---------------- SineEncoding (+ zeroing the pool accumulators) ----------------
// eeig[token][0]=eva, [1..64]=sin(pe), [65..128]=cos(pe), [129..131]=0
__global__ void eeig_kernel(const float* __restrict__ eva) {
    int token = blockIdx.x;
    int j = threadIdx.x;
    if (blockIdx.x == 0) {                      // fold pool zeroing into this launch
        for (int t = j; t < BB*20; t += 160) g_pool[t] = 0.f;
    }
    if (j >= KPAD) return;
    float e = eva[token];
    float v;
    if (j == 0) {
        v = e;
    } else if (j < 65) {
        int m = j - 1;
        float div = expf((float)(2*m) * (-9.210340371976184f / 128.f)); // -ln(1e4)/D
        v = sinf(e * 100.f * div);
    } else if (j < 129) {
        int m = j - 65;
        float div = expf((float)(2*m) * (-9.210340371976184f / 128.f));
        v = cosf(e * 100.f * div);
    } else {
        v = 0.f;
    }
    g_eeig[(long)token * KPAD + j] = v;
}

// LayerNorm over D=128: one warp per row
__global__ void ln_kernel(const float* __restrict__ x,
                          const float* __restrict__ sc,
                          const float* __restrict__ bi,
                          float* __restrict__ o) {
    int row = blockIdx.x * 8 + (threadIdx.x >> 5);
    int lane = threadIdx.x & 31;
    const float4* xp = (const float4*)(x + (long)row * DD);
    float4 v = xp[lane];
    float s = v.x + v.y + v.z + v.w;
    #pragma unroll
    for (int off = 16; off; off >>= 1) s += __shfl_xor_sync(0xffffffffu, s, off);
    float m = s * (1.f / 128.f);
    float dx = v.x - m, dy = v.y - m, dz = v.z - m, dw = v.w - m;
    float vs = dx*dx + dy*dy + dz*dz + dw*dw;
    #pragma unroll
    for (int off = 16; off; off >>= 1) vs += __shfl_xor_sync(0xffffffffu, vs, off);
    float inv = rsqrtf(vs * (1.f / 128.f) + 1e-5f);
    float4 sv = ((const float4*)sc)[lane];
    float4 bv = ((const float4*)bi)[lane];
    float4 r;
    r.x = dx * inv * sv.x + bv.x;
    r.y = dy * inv * sv.y + bv.y;
    r.z = dz * inv * sv.z + bv.z;
    r.w = dw * inv * sv.w + bv.w;
    ((float4*)(o + (long)row * DD))[lane] = r;
}

// ---------------- fp32x2 GEMM: out[r][c] = act(sum_k A[r][k]*W[c][k] + bias[c]) (+resid) ----------------
// 128x128 output tile per block, 256 threads, 8x8 microtile via FFMA2 pairs.
__global__ __launch_bounds__(256, 1)
void gemm128(const float* __restrict__ A, int lda, int ka,
             const float* __restrict__ W, int ldw, int kw,
             const float* __restrict__ bias,
             const float* __restrict__ resid,
             float* __restrict__ out, int ldo, int act)
{
    extern __shared__ float sm[];
    float* As = sm;                 // [k][r] k-major, stride KPAD
    float* Ws = sm + KPAD * KPAD;   // [k][c]
    int tid = threadIdx.x;
    int row0 = blockIdx.x * 128, col0 = blockIdx.y * 128;

    for (int idx = tid; idx < 128 * KPAD; idx += 256) {
        int r = idx / KPAD, k = idx - r * KPAD;
        As[k * KPAD + r] = (k < ka) ? A[(long)(row0 + r) * lda + k] : 0.f;
        Ws[k * KPAD + r] = (k < kw) ? W[(long)(col0 + r) * ldw + k] : 0.f;
    }
    __syncthreads();

    int ty = tid >> 4, tx = tid & 15;
    ull acc2[8][4];
    #pragma unroll
    for (int i = 0; i < 8; i++)
        #pragma unroll
        for (int j = 0; j < 4; j++) acc2[i][j] = 0ull;

    const float4* As4 = (const float4*)As;
    const ulonglong2* Wsu = (const ulonglong2*)Ws;
    #pragma unroll 4
    for (int k = 0; k < KPAD; ++k) {
        float4 a0 = As4[k * (KPAD/4) + ty * 2];
        float4 a1 = As4[k * (KPAD/4) + ty * 2 + 1];
        ulonglong2 wA = Wsu[k * (KPAD/4) + tx * 2];      // (w0,w1),(w2,w3)
        ulonglong2 wB = Wsu[k * (KPAD/4) + tx * 2 + 1];  // (w4,w5),(w6,w7)
        float a[8] = {a0.x,a0.y,a0.z,a0.w,a1.x,a1.y,a1.z,a1.w};
        #pragma unroll
        for (int i = 0; i < 8; i++) {
            ull ba = pack2(a[i], a[i]);
            acc2[i][0] = fma2(ba, wA.x, acc2[i][0]);
            acc2[i][1] = fma2(ba, wA.y, acc2[i][1]);
            acc2[i][2] = fma2(ba, wB.x, acc2[i][2]);
            acc2[i][3] = fma2(ba, wB.y, acc2[i][3]);
        }
    }

    #pragma unroll
    for (int i = 0; i < 8; i++) {
        int r = row0 + ty * 8 + i;
        #pragma unroll
        for (int j2 = 0; j2 < 4; j2++) {
            int c = col0 + tx * 8 + j2 * 2;
            float v0, v1;
            unpack2(acc2[i][j2], v0, v1);
            v0 += bias[c]; v1 += bias[c + 1];
            if (act) {
                v0 = 0.5f * v0 * (1.f + erff(v0 * 0.70710678118654752f));
                v1 = 0.5f * v1 * (1.f + erff(v1 * 0.70710678118654752f));
            }
            if (resid) {
                v0 += resid[(long)r * ldo + c];
                v1 += resid[(long)r * ldo + c + 1];
            }
            float2 st; st.x = v0; st.y = v1;
            *(float2*)(out + (long)r * ldo + c) = st;
        }
    }
}

// ---------------- attention: one block per (b,h); one query per lane, broadcast K/V ----------------
// Inner loop: 2 keys/iter, 2 parallel score chains per key -> 4 independent 4-deep
// FFMA2 chains (RAW-latency hidden; fma-pipe throughput is the binding constraint).
__global__ __launch_bounds__(256, 1)
void attn_kernel(const int* __restrict__ length)
{
    extern __shared__ float sm[];
    float* Ks = sm;               // [1024][16]
    float* Vs = sm + NN * DH;     // [1024][16]
    int b = blockIdx.x >> 3, h = blockIdx.x & 7;
    int tid = threadIdx.x, lane = tid & 31, wid = tid >> 5;

    // stage K and V for this head (coalesced 64B runs)
    for (int idx = tid; idx < NN * DH; idx += 256) {
        int key = idx >> 4, d = idx & 15;
        long g = (long)(b * NN + key) * (3*DD) + DD + h * DH + d;
        Ks[idx] = g_qkv[g];
        Vs[idx] = g_qkv[g + DD];
    }
    __syncthreads();

    int len = length[b];

    // 4 scans x 256 threads = 1024 queries; each lane owns one query end-to-end.
    for (int scan = 0; scan < 4; ++scan) {
        int q = scan * 256 + wid * 32 + lane;
        const float4* qp = (const float4*)(g_qkv + (long)(b * NN + q) * (3*DD) + h * DH);
        ull q2[8];
        #pragma unroll
        for (int r = 0; r < 4; r++) {
            float4 t = qp[r];
            q2[2*r]   = pack2(t.x * 0.25f, t.y * 0.25f);  // 1/sqrt(dh)
            q2[2*r+1] = pack2(t.z * 0.25f, t.w * 0.25f);
        }
        ull acc2[8];
        #pragma unroll
        for (int d = 0; d < 8; d++) acc2[d] = 0ull;
        float l = 0.f;

        int key = 0;
        for (; key + 2 <= len; key += 2) {
            const ulonglong2* kp0 = (const ulonglong2*)(Ks + (key << 4));
            const ulonglong2* kp1 = (const ulonglong2*)(Ks + ((key + 1) << 4));
            ulonglong2 k0A = kp0[0], k0B = kp0[1], k0C = kp0[2], k0D = kp0[3];
            ulonglong2 k1A = kp1[0], k1B = kp1[1], k1C = kp1[2], k1D = kp1[3];

            // key0: two parallel 4-deep chains
            ull sa0 = mul2(q2[0], k0A.x);
            ull sb0 = mul2(q2[1], k0A.y);
            sa0 = fma2(q2[2], k0B.x, sa0);
            sb0 = fma2(q2[3], k0B.y, sb0);
            sa0 = fma2(q2[4], k0C.x, sa0);
            sb0 = fma2(q2[5], k0C.y, sb0);
            sa0 = fma2(q2[6], k0D.x, sa0);
            sb0 = fma2(q2[7], k0D.y, sb0);
            // key1
            ull sa1 = mul2(q2[0], k1A.x);
            ull sb1 = mul2(q2[1], k1A.y);
            sa1 = fma2(q2[2], k1B.x, sa1);
            sb1 = fma2(q2[3], k1B.y, sb1);
            sa1 = fma2(q2[4], k1C.x, sa1);
            sb1 = fma2(q2[5], k1C.y, sb1);
            sa1 = fma2(q2[6], k1D.x, sa1);
            sb1 = fma2(q2[7], k1D.y, sb1);

            float xa0, ya0, xb0, yb0, xa1, ya1, xb1, yb1;
            unpack2(sa0, xa0, ya0); unpack2(sb0, xb0, yb0);
            unpack2(sa1, xa1, ya1); unpack2(sb1, xb1, yb1);
            // scores tiny (|s| << 1): exp(s) with skipped masked keys equals the
            // reference max-shifted softmax (exp(-1e9 - m) == 0 in fp32).
            float p0 = __expf((xa0 + ya0) + (xb0 + yb0));
            float p1 = __expf((xa1 + ya1) + (xb1 + yb1));
            l += p0 + p1;
            ull pp0 = pack2(p0, p0), pp1 = pack2(p1, p1);

            const ulonglong2* vp0 = (const ulonglong2*)(Vs + (key << 4));
            const ulonglong2* vp1 = (const ulonglong2*)(Vs + ((key + 1) << 4));
            ulonglong2 v0A = vp0[0], v0B = vp0[1], v0C = vp0[2], v0D = vp0[3];
            ulonglong2 v1A = vp1[0], v1B = vp1[1], v1C = vp1[2], v1D = vp1[3];
            acc2[0] = fma2(pp0, v0A.x, acc2[0]);
            acc2[1] = fma2(pp0, v0A.y, acc2[1]);
            acc2[2] = fma2(pp0, v0B.x, acc2[2]);
            acc2[3] = fma2(pp0, v0B.y, acc2[3]);
            acc2[4] = fma2(pp0, v0C.x, acc2[4]);
            acc2[5] = fma2(pp0, v0C.y, acc2[5]);
            acc2[6] = fma2(pp0, v0D.x, acc2[6]);
            acc2[7] = fma2(pp0, v0D.y, acc2[7]);
            acc2[0] = fma2(pp1, v1A.x, acc2[0]);
            acc2[1] = fma2(pp1, v1A.y, acc2[1]);
            acc2[2] = fma2(pp1, v1B.x, acc2[2]);
            acc2[3] = fma2(pp1, v1B.y, acc2[3]);
            acc2[4] = fma2(pp1, v1C.x, acc2[4]);
            acc2[5] = fma2(pp1, v1C.y, acc2[5]);
            acc2[6] = fma2(pp1, v1D.x, acc2[6]);
            acc2[7] = fma2(pp1, v1D.y, acc2[7]);
        }
        if (key < len) {  // odd tail
            const ulonglong2* kp = (const ulonglong2*)(Ks + (key << 4));
            ulonglong2 kA = kp[0], kB = kp[1], kC = kp[2], kD = kp[3];
            ull sa = mul2(q2[0], kA.x);
            ull sb = mul2(q2[1], kA.y);
            sa = fma2(q2[2], kB.x, sa);
            sb = fma2(q2[3], kB.y, sb);
            sa = fma2(q2[4], kC.x, sa);
            sb = fma2(q2[5], kC.y, sb);
            sa = fma2(q2[6], kD.x, sa);
            sb = fma2(q2[7], kD.y, sb);
            float xa, ya, xb, yb;
            unpack2(sa, xa, ya); unpack2(sb, xb, yb);
            float p = __expf((xa + ya) + (xb + yb));
            l += p;
            ull pp = pack2(p, p);
            const ulonglong2* vp = (const ulonglong2*)(Vs + (key << 4));
            ulonglong2 vA = vp[0], vB = vp[1], vC = vp[2], vD = vp[3];
            acc2[0] = fma2(pp, vA.x, acc2[0]);
            acc2[1] = fma2(pp, vA.y, acc2[1]);
            acc2[2] = fma2(pp, vB.x, acc2[2]);
            acc2[3] = fma2(pp, vB.y, acc2[3]);
            acc2[4] = fma2(pp, vC.x, acc2[4]);
            acc2[5] = fma2(pp, vC.y, acc2[5]);
            acc2[6] = fma2(pp, vD.x, acc2[6]);
            acc2[7] = fma2(pp, vD.y, acc2[7]);
        }

        float invl = 1.f / l;
        float* op = g_att + (long)(b * NN + q) * DD + h * DH;
        #pragma unroll
        for (int j = 0; j < 4; j++) {
            float x0, y0, x1, y1;
            unpack2(acc2[2*j],   x0, y0);
            unpack2(acc2[2*j+1], x1, y1);
            float4 st;
            st.x = x0 * invl; st.y = y0 * invl; st.z = x1 * invl; st.w = y1 * invl;
            ((float4*)op)[j] = st;
        }
    }
}

// ---------------- pooled decoders: sum_{n<len} eig[b][n] @ W_o ----------------
__global__ void pooled_kernel(const int* __restrict__ length,
                              const float* __restrict__ W_sca,
                              const float* __restrict__ W_wav,
                              const float* __restrict__ W_scl)
{
    __shared__ float red[20][129];
    int b = blockIdx.x >> 3, chunk = blockIdx.x & 7;
    int d = threadIdx.x;    // 128 threads
    int len = length[b];

    float w[20];
    #pragma unroll
    for (int o = 0; o < 8; o++) w[o]      = W_sca[o * DD + d];
    #pragma unroll
    for (int o = 0; o < 8; o++) w[8 + o]  = W_wav[o * DD + d];
    #pragma unroll
    for (int o = 0; o < 4; o++) w[16 + o] = W_scl[o * DD + d];

    float part[20];
    #pragma unroll
    for (int o = 0; o < 20; o++) part[o] = 0.f;

    int n0 = chunk * 128;
    int nend = len - n0; if (nend > 128) nend = 128; if (nend < 0) nend = 0;
    for (int nn = 0; nn < nend; ++nn) {
        float x = g_eig[(long)((b << 10) + n0 + nn) * DD + d];
        #pragma unroll
        for (int o = 0; o < 20; o++) part[o] = fmaf(x, w[o], part[o]);
    }
    #pragma unroll
    for (int o = 0; o < 20; o++) red[o][d] = part[o];
    __syncthreads();
    if (d < 20) {
        float s = 0.f;
        for (int i = 0; i < 128; i++) s += red[d][i];
        atomicAdd(&g_pool[b * 20 + d], s);
    }
}

__device__ __forceinline__ float sigm(float x) { return 1.f / (1.f + expf(-x)); }

__global__ void coe_kernel(const int* __restrict__ length,
                           const float* __restrict__ b_sca,
                           const float* __restrict__ b_wav,
                           const float* __restrict__ b_scl)
{
    int b = threadIdx.x;
    if (b >= BB) return;
    float len = (float)length[b];
    float inv = 1.f / (len + 1e-8f);
    float sca[8], wav[8];
    float ssum = 0.f, wsum = 0.f;
    #pragma unroll
    for (int o = 0; o < 8; o++) {
        sca[o] = sigm((g_pool[b*20 + o]     + len * b_sca[o]) * inv); ssum += sca[o];
        wav[o] = sigm((g_pool[b*20 + 8 + o] + len * b_wav[o]) * inv); wsum += wav[o];
    }
    #pragma unroll
    for (int o = 0; o < 8; o++) {
        g_coe[b*20 + o]     = sca[o] / (ssum + 1e-8f);
        g_coe[b*20 + 8 + o] = wav[o] / (wsum + 1e-8f);
    }
    #pragma unroll
    for (int j = 0; j < 4; j++)
        g_coe[b*20 + 16 + j] = 2.f * sigm((g_pool[b*20 + 16 + j] + len * b_scl[j]) * inv);
}

// ---------------- final output: Chebyshev bases + tight-frame normalization ----------------
__global__ void out_kernel(const float* __restrict__ eva, float* __restrict__ out)
{
    int t = blockIdx.x * 256 + threadIdx.x;
    if (t >= NTOK) return;
    int b = t >> 10;
    float e = eva[t];
    const float* coe = g_coe + b * 20;

    // scaling: odd Chebyshev T_{2i+1}(e-1)
    float y = e - 1.f;
    float te = 1.f, to = y;
    float s_acc = coe[0] * 0.5f * (1.f - to);
    #pragma unroll
    for (int i = 1; i < 8; i++) {
        te = 2.f * y * to - te;
        to = 2.f * y * te - to;
        s_acc += coe[i] * 0.5f * (1.f - to);
    }
    // wavelets: even Chebyshev T_{2i}(fsw-1), fsw = e*coe_scl[j] zeroed if >2
    float wacc[4];
    #pragma unroll
    for (int j = 0; j < 4; j++) {
        float f = e * coe[16 + j];
        if (f > 2.f) f = 0.f;
        float yy = f - 1.f;
        float te2 = 1.f, to2 = yy;
        float a = coe[8] * 0.5f * (1.f - te2);   // T0 term (== 0, kept faithful)
        #pragma unroll
        for (int i = 1; i < 8; i++) {
            te2 = 2.f * yy * to2 - te2;
            to2 = 2.f * yy * te2 - to2;
            a += coe[8 + i] * 0.5f * (1.f - te2);
        }
        wacc[j] = a;
    }
    float nrm = s_acc * s_acc;
    #pragma unroll
    for (int j = 0; j < 4; j++) nrm += wacc[j] * wacc[j];
    float invn = 1.f / (sqrtf(nrm) + 1e-8f);
    float* op = out + (long)t * 5;
    op[0] = s_acc * invn;
    #pragma unroll
    for (int j = 0; j < 4; j++) op[1 + j] = wacc[j] * invn;
}

// ---------------- host orchestration ----------------
extern "C" void kernel_launch(void* const* d_in, const int* in_sizes, int n_in,
                              void* d_out, int out_size)
{
    const float* eva      = (const float*)d_in[1];
    const int*   length   = (const int*)  d_in[2];
    const float* eig_w_W  = (const float*)d_in[3];
    const float* eig_w_b  = (const float*)d_in[4];
    const float* ln1_s    = (const float*)d_in[5];
    const float* ln1_b    = (const float*)d_in[6];
    const float* ln2_s    = (const float*)d_in[7];
    const float* ln2_b    = (const float*)d_in[8];
    const float* qkv_W    = (const float*)d_in[9];
    const float* qkv_b    = (const float*)d_in[10];
    const float* out_W    = (const float*)d_in[11];
    const float* out_b    = (const float*)d_in[12];
    const float* ffn_W1   = (const float*)d_in[13];
    const float* ffn_b1   = (const float*)d_in[14];
    const float* ffn_W2   = (const float*)d_in[15];
    const float* ffn_b2   = (const float*)d_in[16];
    const float* dec_sca_W = (const float*)d_in[17];
    const float* dec_sca_b = (const float*)d_in[18];
    const float* dec_wav_W = (const float*)d_in[19];
    const float* dec_wav_b = (const float*)d_in[20];
    const float* dec_scl_W = (const float*)d_in[21];
    const float* dec_scl_b = (const float*)d_in[22];
    float* out = (float*)d_out;

    const int SMEM_G = 2 * KPAD * KPAD * 4;   // 139392 B
    const int SMEM_A = 2 * NN * DH * 4;       // 131072 B
    cudaFuncSetAttribute(gemm128,     cudaFuncAttributeMaxDynamicSharedMemorySize, SMEM_G);
    cudaFuncSetAttribute(attn_kernel, cudaFuncAttributeMaxDynamicSharedMemorySize, SMEM_A);

    void *p_eeig, *p_eig, *p_h, *p_qkv, *p_att;
    cudaGetSymbolAddress(&p_eeig, g_eeig);
    cudaGetSymbolAddress(&p_eig,  g_eig);
    cudaGetSymbolAddress(&p_h,    g_h);
    cudaGetSymbolAddress(&p_qkv,  g_qkv);
    cudaGetSymbolAddress(&p_att,  g_att);

    eeig_kernel<<<NTOK, 160>>>(eva);

    // eig = eeig @ eig_w_W.T + b
    gemm128<<<dim3(128, 1), 256, SMEM_G>>>((const float*)p_eeig, KPAD, KPAD,
                                           eig_w_W, 129, 129, eig_w_b,
                                           nullptr, (float*)p_eig, DD, 0);
    // h = LN1(eig)
    ln_kernel<<<NTOK/8, 256>>>((const float*)p_eig, ln1_s, ln1_b, (float*)p_h);
    // qkv = h @ qkv_W.T + b
    gemm128<<<dim3(128, 3), 256, SMEM_G>>>((const float*)p_h, DD, DD,
                                           qkv_W, DD, DD, qkv_b,
                                           nullptr, (float*)p_qkv, 3*DD, 0);
    // attention
    attn_kernel<<<BB*HH, 256, SMEM_A>>>(length);
    // eig += att @ out_W.T + b
    gemm128<<<dim3(128, 1), 256, SMEM_G>>>((const float*)p_att, DD, DD,
                                           out_W, DD, DD, out_b,
                                           (const float*)p_eig, (float*)p_eig, DD, 0);
    // h = LN2(eig)
    ln_kernel<<<NTOK/8, 256>>>((const float*)p_eig, ln2_s, ln2_b, (float*)p_h);
    // f = gelu(h @ ffn_W1.T + b1)
    gemm128<<<dim3(128, 1), 256, SMEM_G>>>((const float*)p_h, DD, DD,
                                           ffn_W1, DD, DD, ffn_b1,
                                           nullptr, (float*)p_att, DD, 1);
    // eig += f @ ffn_W2.T + b2
    gemm128<<<dim3(128, 1), 256, SMEM_G>>>((const float*)p_att, DD, DD,
                                           ffn_W2, DD, DD, ffn_b2,
                                           (const float*)p_eig, (float*)p_eig, DD, 0);
    // pooled decoders -> coefficients
    pooled_kernel<<<BB*8, 128>>>(length, dec_sca_W, dec_wav_W, dec_scl_W);
    coe_kernel<<<1, 32>>>(length, dec_sca_b, dec_wav_b, dec_scl_b);
    // final Chebyshev output
    out_kernel<<<NTOK/256, 256>>>(eva, out);
}